// round 17
// baseline (speedup 1.0000x reference)
#include <cuda_runtime.h>
#include <cstdint>
#include <math.h>

#define Bb 2
#define Ss 2048
#define Hh 1024
#define NHh 16
#define Dd 64
#define MROWS (Bb * Ss)   // 4096

typedef unsigned long long ull;

// Scratch (no cudaMalloc allowed): Q, K, V, ctx each [4096, 1024] fp32 = 16 MiB
__device__ float g_q[MROWS * Hh];
__device__ float g_k[MROWS * Hh];
__device__ float g_v[MROWS * Hh];
__device__ float g_ctx[MROWS * Hh];

// ===========================================================================
// f32x2 packed-math helpers
// ===========================================================================
__device__ __forceinline__ ull pk2(float x, float y) {
    ull r;
    asm("mov.b64 %0, {%1, %2};" : "=l"(r) : "f"(x), "f"(y));
    return r;
}
__device__ __forceinline__ void upk2(ull v, float& x, float& y) {
    asm("mov.b64 {%0, %1}, %2;" : "=f"(x), "=f"(y) : "l"(v));
}
__device__ __forceinline__ ull ffma2(ull a, ull b, ull c) {
    ull d;
    asm("fma.rn.f32x2 %0, %1, %2, %3;" : "=l"(d) : "l"(a), "l"(b), "l"(c));
    return d;
}
__device__ __forceinline__ ull fmul2(ull a, ull b) {
    ull d;
    asm("mul.rn.f32x2 %0, %1, %2;" : "=l"(d) : "l"(a), "l"(b));
    return d;
}

// ===========================================================================
// GEMM core — R8 skeleton (256 thr, 128x128 tile, K-tile 16, 8x8/thread,
// double-buffered, 2 CTAs/SM) with A stored PRE-DUPLICATED as (a,a) f32x2
// pairs in smem: the 8 pk2 MOVs leave the inner loop (16x/kk -> 1x/tile).
// A stride 134 ull: even (16B-aligned LDS128 rows) and <=2-way STS conflicts.
// C[m][n] = sum_k A[m][k]*W[n][k] + bias[n].  M=4096, N=1024, K=1024.
// ===========================================================================
#define ASTR 134                                   // ull stride per kk row
#define GS_A_BYTES (2 * 16 * ASTR * 8)             // 34304
#define GS_B_OFF   GS_A_BYTES
#define SMEM_GEMM  (GS_B_OFF + 2 * 16 * 132 * 4)   // 51200

__device__ __forceinline__ void gemm_core(
    const float* __restrict__ A, const float* __restrict__ W,
    const float* __restrict__ bias, float* __restrict__ C,
    char* smem_raw)
{
    ull*   As = (ull*)smem_raw;                    // [buf][kk][m] dup pairs
    float* Bs = (float*)(smem_raw + GS_B_OFF);     // [buf][kk][n]

    const int K = 1024, N = 1024;
    const int tid = threadIdx.x;
    const int tx = tid % 16;          // n direction
    const int ty = tid / 16;          // m direction
    const int m0 = blockIdx.y * 128;
    const int n0 = blockIdx.x * 128;
    const int lr = tid / 4;           // 0..63
    const int lc = (tid % 4) * 4;     // 0,4,8,12

    ull acc2[8][4];
#pragma unroll
    for (int i = 0; i < 8; i++)
#pragma unroll
        for (int j = 0; j < 4; j++) acc2[i][j] = 0ULL;

    const float* Arow0 = A + (size_t)(m0 + lr) * K + lc;
    const float* Arow1 = A + (size_t)(m0 + lr + 64) * K + lc;
    const float* Brow0 = W + (size_t)(n0 + lr) * K + lc;
    const float* Brow1 = W + (size_t)(n0 + lr + 64) * K + lc;

    // prefetch + store tile 0
    {
        float4 a0 = *(const float4*)Arow0;
        float4 a1 = *(const float4*)Arow1;
        float4 b0 = *(const float4*)Brow0;
        float4 b1 = *(const float4*)Brow1;
        As[(lc + 0) * ASTR + lr] = pk2(a0.x, a0.x);
        As[(lc + 1) * ASTR + lr] = pk2(a0.y, a0.y);
        As[(lc + 2) * ASTR + lr] = pk2(a0.z, a0.z);
        As[(lc + 3) * ASTR + lr] = pk2(a0.w, a0.w);
        As[(lc + 0) * ASTR + lr + 64] = pk2(a1.x, a1.x);
        As[(lc + 1) * ASTR + lr + 64] = pk2(a1.y, a1.y);
        As[(lc + 2) * ASTR + lr + 64] = pk2(a1.z, a1.z);
        As[(lc + 3) * ASTR + lr + 64] = pk2(a1.w, a1.w);
        Bs[(lc + 0) * 132 + lr] = b0.x;
        Bs[(lc + 1) * 132 + lr] = b0.y;
        Bs[(lc + 2) * 132 + lr] = b0.z;
        Bs[(lc + 3) * 132 + lr] = b0.w;
        Bs[(lc + 0) * 132 + lr + 64] = b1.x;
        Bs[(lc + 1) * 132 + lr + 64] = b1.y;
        Bs[(lc + 2) * 132 + lr + 64] = b1.z;
        Bs[(lc + 3) * 132 + lr + 64] = b1.w;
    }
    __syncthreads();

    for (int t = 0; t < 64; t++) {
        const int cur = t & 1;
        const ull*   ac = As + cur * (16 * ASTR);
        const float* bc = Bs + cur * (16 * 132);
        float4 na0, na1, nb0, nb1;
        if (t < 63) {
            int k1 = (t + 1) * 16;
            na0 = *(const float4*)&Arow0[k1];
            na1 = *(const float4*)&Arow1[k1];
            nb0 = *(const float4*)&Brow0[k1];
            nb1 = *(const float4*)&Brow1[k1];
        }

#pragma unroll
        for (int kk = 0; kk < 16; kk++) {
            const ull* ap = &ac[kk * ASTR + ty * 8];
            ulonglong2 t0 = *(const ulonglong2*)(ap + 0);
            ulonglong2 t1 = *(const ulonglong2*)(ap + 2);
            ulonglong2 t2 = *(const ulonglong2*)(ap + 4);
            ulonglong2 t3 = *(const ulonglong2*)(ap + 6);
            ull ra2[8] = {t0.x, t0.y, t1.x, t1.y, t2.x, t2.y, t3.x, t3.y};
            ull rb2[4];
#pragma unroll
            for (int j = 0; j < 4; j++)
                rb2[j] = *(const ull*)&bc[kk * 132 + 2 * tx + 32 * j];
#pragma unroll
            for (int i = 0; i < 8; i++)
#pragma unroll
                for (int j = 0; j < 4; j++)
                    acc2[i][j] = ffma2(ra2[i], rb2[j], acc2[i][j]);
        }

        if (t < 63) {
            ull*   an = As + (cur ^ 1) * (16 * ASTR);
            float* bn = Bs + (cur ^ 1) * (16 * 132);
            an[(lc + 0) * ASTR + lr] = pk2(na0.x, na0.x);
            an[(lc + 1) * ASTR + lr] = pk2(na0.y, na0.y);
            an[(lc + 2) * ASTR + lr] = pk2(na0.z, na0.z);
            an[(lc + 3) * ASTR + lr] = pk2(na0.w, na0.w);
            an[(lc + 0) * ASTR + lr + 64] = pk2(na1.x, na1.x);
            an[(lc + 1) * ASTR + lr + 64] = pk2(na1.y, na1.y);
            an[(lc + 2) * ASTR + lr + 64] = pk2(na1.z, na1.z);
            an[(lc + 3) * ASTR + lr + 64] = pk2(na1.w, na1.w);
            bn[(lc + 0) * 132 + lr] = nb0.x;
            bn[(lc + 1) * 132 + lr] = nb0.y;
            bn[(lc + 2) * 132 + lr] = nb0.z;
            bn[(lc + 3) * 132 + lr] = nb0.w;
            bn[(lc + 0) * 132 + lr + 64] = nb1.x;
            bn[(lc + 1) * 132 + lr + 64] = nb1.y;
            bn[(lc + 2) * 132 + lr + 64] = nb1.z;
            bn[(lc + 3) * 132 + lr + 64] = nb1.w;
            __syncthreads();
        }
    }

#pragma unroll
    for (int i = 0; i < 8; i++) {
        int row = m0 + ty * 8 + i;
#pragma unroll
        for (int j = 0; j < 4; j++) {
            int col = n0 + 2 * tx + 32 * j;
            float2 bb = *(const float2*)&bias[col];
            float x, y;
            upk2(acc2[i][j], x, y);
            float2 c;
            c.x = x + bb.x;
            c.y = y + bb.y;
            *(float2*)&C[(size_t)row * N + col] = c;
        }
    }
}

// Fused QKV projection: grid.z selects {Q,K,V}
__global__ void __launch_bounds__(256, 2) qkv_f2(
    const float* __restrict__ x,
    const float* __restrict__ wq, const float* __restrict__ bq,
    const float* __restrict__ wk, const float* __restrict__ bk,
    const float* __restrict__ wv, const float* __restrict__ bv)
{
    extern __shared__ char smem_raw[];
    const float* W; const float* bias; float* C;
    if (blockIdx.z == 0)      { W = wq; bias = bq; C = g_q; }
    else if (blockIdx.z == 1) { W = wk; bias = bk; C = g_k; }
    else                      { W = wv; bias = bv; C = g_v; }
    gemm_core(x, W, bias, C, smem_raw);
}

__global__ void __launch_bounds__(256, 2) oproj_f2(
    const float* __restrict__ wo, const float* __restrict__ bo,
    float* __restrict__ out)
{
    extern __shared__ char smem_raw[];
    gemm_core(g_ctx, wo, bo, out, smem_raw);
}

// ===========================================================================
// Flash attention — EXACT R16 version (at FFMA2-pipe floor ~900 us).
// Br=128, Bc=64, D=64, 256 threads, 2 CTAs/SM.
//  - Q ROW-major d-pairs, stride QS=34 ull -> LDS128 loads q for 2 dp at once
//  - P transposed [col][tm*4+i] float4   -> 1 LDS128/k in PV, 8 STS128 total
// tm=tid/8 (0..31), tn=tid%8. Rows {tm+32i}, i<4. QK cols {tn+8c}, c<8.
// ===========================================================================
#define QS  34
#define KPR 65
#define VR  68
#define PS  132
#define OFF_Q  0
#define OFF_K  (128 * QS * 8)                  // 34816
#define OFF_V  (OFF_K + 32 * KPR * 8)          // 51456
#define OFF_P  (OFF_V + 64 * VR * 4)           // 68864
#define SMEM_ATTN (OFF_P + 64 * PS * 4)        // 102656

__global__ void __launch_bounds__(256, 2) attn_f2()
{
    extern __shared__ char smem_raw[];
    ull*   sQ  = (ull*)(smem_raw + OFF_Q);     // [row*QS + dp]
    ull*   sKp = (ull*)(smem_raw + OFF_K);     // [dp*KPR + col]
    float* sV  = (float*)(smem_raw + OFF_V);   // [k*VR + d]
    float* sP  = (float*)(smem_raw + OFF_P);   // [k*PS + tm*4 + i]

    const int bh = blockIdx.y;           // 0..31
    const int b  = bh / NHh;
    const int h  = bh % NHh;
    const int q0 = blockIdx.x * 128;

    const int tid = threadIdx.x;
    const int tm  = tid >> 3;            // 0..31
    const int tn  = tid & 7;             // 0..7

    const float* Qb = g_q + (size_t)(b * Ss) * Hh + h * Dd;
    const float* Kb = g_k + (size_t)(b * Ss) * Hh + h * Dd;
    const float* Vb = g_v + (size_t)(b * Ss) * Hh + h * Dd;

    // Load Q tile (128 rows x 64 d) into ROW-major d-pair layout
    for (int idx = tid; idx < 128 * 16; idx += 256) {
        int r = idx >> 4, f4 = idx & 15;
        float4 v = *(const float4*)&Qb[(size_t)(q0 + r) * Hh + f4 * 4];
        sQ[r * QS + 2 * f4 + 0] = *(ull*)&v.x;
        sQ[r * QS + 2 * f4 + 1] = *(ull*)&v.z;
    }

    float m[4], l[4];
    ull o2[4][4];
#pragma unroll
    for (int i = 0; i < 4; i++) {
        m[i] = -1e30f; l[i] = 0.f;
#pragma unroll
        for (int c = 0; c < 4; c++) o2[i][c] = 0ULL;
    }

    for (int kt = 0; kt < Ss; kt += 64) {
        __syncthreads();   // prev PV done with sKp/sV/sP; Q stores visible
        for (int idx = tid; idx < 64 * 16; idx += 256) {
            int r = idx >> 4, f4 = idx & 15;
            float4 kv = *(const float4*)&Kb[(size_t)(kt + r) * Hh + f4 * 4];
            sKp[(2 * f4 + 0) * KPR + r] = *(ull*)&kv.x;
            sKp[(2 * f4 + 1) * KPR + r] = *(ull*)&kv.z;
            float4 vv = *(const float4*)&Vb[(size_t)(kt + r) * Hh + f4 * 4];
            *(float4*)&sV[r * VR + f4 * 4] = vv;
        }
        __syncthreads();

        // ---- S = Q K^T  (4 rows x 8 cols per thread, 2 dp per step) ----
        ull s2[4][8];
#pragma unroll
        for (int i = 0; i < 4; i++)
#pragma unroll
            for (int c = 0; c < 8; c++) s2[i][c] = 0ULL;

#pragma unroll 4
        for (int dp = 0; dp < 32; dp += 2) {
            ulonglong2 q01[4];
#pragma unroll
            for (int i = 0; i < 4; i++)
                q01[i] = *(const ulonglong2*)&sQ[(tm + 32 * i) * QS + dp];
            ull k2a[8], k2b[8];
#pragma unroll
            for (int c = 0; c < 8; c++) {
                k2a[c] = sKp[(dp + 0) * KPR + tn + 8 * c];
                k2b[c] = sKp[(dp + 1) * KPR + tn + 8 * c];
            }
#pragma unroll
            for (int i = 0; i < 4; i++)
#pragma unroll
                for (int c = 0; c < 8; c++) {
                    s2[i][c] = ffma2(q01[i].x, k2a[c], s2[i][c]);
                    s2[i][c] = ffma2(q01[i].y, k2b[c], s2[i][c]);
                }
        }

        // ---- online softmax (per row; reduce across 8 tn lanes) ----
        float p[4][8];
#pragma unroll
        for (int i = 0; i < 4; i++) {
            float s[8];
            float mrow = -1e30f;
#pragma unroll
            for (int c = 0; c < 8; c++) {
                float lo, hi;
                upk2(s2[i][c], lo, hi);
                s[c] = (lo + hi) * 0.125f;     // 1/sqrt(64)
                mrow = fmaxf(mrow, s[c]);
            }
            mrow = fmaxf(mrow, __shfl_xor_sync(0xffffffffu, mrow, 1));
            mrow = fmaxf(mrow, __shfl_xor_sync(0xffffffffu, mrow, 2));
            mrow = fmaxf(mrow, __shfl_xor_sync(0xffffffffu, mrow, 4));

            float mnew  = fmaxf(m[i], mrow);
            float alpha = __expf(m[i] - mnew);
            float lsum = 0.f;
#pragma unroll
            for (int c = 0; c < 8; c++) {
                p[i][c] = __expf(s[c] - mnew);
                lsum += p[i][c];
            }
            lsum += __shfl_xor_sync(0xffffffffu, lsum, 1);
            lsum += __shfl_xor_sync(0xffffffffu, lsum, 2);
            lsum += __shfl_xor_sync(0xffffffffu, lsum, 4);
            l[i] = l[i] * alpha + lsum;
            m[i] = mnew;
            ull a2 = pk2(alpha, alpha);
#pragma unroll
            for (int c = 0; c < 4; c++) o2[i][c] = fmul2(o2[i][c], a2);
        }

        // ---- store P transposed: one float4 (4 rows) per column ----
#pragma unroll
        for (int c = 0; c < 8; c++) {
            float4 pf;
            pf.x = p[0][c]; pf.y = p[1][c]; pf.z = p[2][c]; pf.w = p[3][c];
            *(float4*)&sP[(tn + 8 * c) * PS + tm * 4] = pf;
        }
        __syncthreads();   // sP fully written

        // ---- O += P V  (1 LDS128 for 4 rows' p, 4 LDS64 for v, per k) ----
#pragma unroll 4
        for (int k = 0; k < 64; k++) {
            float4 pf = *(const float4*)&sP[k * PS + tm * 4];
            ull v2[4];
#pragma unroll
            for (int c = 0; c < 4; c++)
                v2[c] = *(const ull*)&sV[k * VR + 2 * tn + 16 * c];
            ull p2;
            p2 = pk2(pf.x, pf.x);
#pragma unroll
            for (int c = 0; c < 4; c++) o2[0][c] = ffma2(p2, v2[c], o2[0][c]);
            p2 = pk2(pf.y, pf.y);
#pragma unroll
            for (int c = 0; c < 4; c++) o2[1][c] = ffma2(p2, v2[c], o2[1][c]);
            p2 = pk2(pf.z, pf.z);
#pragma unroll
            for (int c = 0; c < 4; c++) o2[2][c] = ffma2(p2, v2[c], o2[2][c]);
            p2 = pk2(pf.w, pf.w);
#pragma unroll
            for (int c = 0; c < 4; c++) o2[3][c] = ffma2(p2, v2[c], o2[3][c]);
        }
    }

    // Epilogue: normalize and write to concat layout [B*S, H]
#pragma unroll
    for (int i = 0; i < 4; i++) {
        const float inv = 1.f / l[i];
        const int row = q0 + tm + 32 * i;
        float* op = g_ctx + (size_t)(b * Ss + row) * Hh + h * Dd;
#pragma unroll
        for (int c = 0; c < 4; c++) {
            float x, y;
            upk2(o2[i][c], x, y);
            float2 w;
            w.x = x * inv; w.y = y * inv;
            *(float2*)&op[2 * tn + 16 * c] = w;
        }
    }
}

// ---------------------------------------------------------------------------
extern "C" void kernel_launch(void* const* d_in, const int* in_sizes, int n_in,
                              void* d_out, int out_size)
{
    const float* x  = (const float*)d_in[0];
    const float* wq = (const float*)d_in[1];
    const float* bq = (const float*)d_in[2];
    const float* wk = (const float*)d_in[3];
    const float* bk = (const float*)d_in[4];
    const float* wv = (const float*)d_in[5];
    const float* bv = (const float*)d_in[6];
    const float* wo = (const float*)d_in[7];
    const float* bo = (const float*)d_in[8];
    float* out = (float*)d_out;

    cudaFuncSetAttribute(attn_f2, cudaFuncAttributeMaxDynamicSharedMemorySize,
                         SMEM_ATTN);
    cudaFuncSetAttribute(qkv_f2, cudaFuncAttributeMaxDynamicSharedMemorySize,
                         SMEM_GEMM);
    cudaFuncSetAttribute(oproj_f2, cudaFuncAttributeMaxDynamicSharedMemorySize,
                         SMEM_GEMM);

    dim3 gq(1024 / 128, MROWS / 128, 3);   // (8, 32, 3)
    qkv_f2<<<gq, 256, SMEM_GEMM>>>(x, wq, bq, wk, bk, wv, bv);

    dim3 ga(Ss / 128, Bb * NHh);           // (16, 32)
    attn_f2<<<ga, 256, SMEM_ATTN>>>();

    dim3 gg(1024 / 128, MROWS / 128);      // (8, 32)
    oproj_f2<<<gg, 256, SMEM_GEMM>>>(wo, bo, out);
}